// round 7
// baseline (speedup 1.0000x reference)
#include <cuda_runtime.h>
#include <cuda_fp16.h>
#include <stdint.h>

#define FDIM   1024
#define BATCH  256
#define NCLS   1000
#define CPAD   1024
#define KROW   65536
#define CB     16          // class blocks of 64
#define FS     8           // f slices of 128
#define FPC    128
#define THREADS 256
#define TSTRIDE 65         // tile row stride in words

// ---------------- static device scratch ----------------
__device__ uint2 g_meta[FDIM * BATCH];                   // [f][b]: {t*260, half2(1-l0, l0)}
__device__ float g_part[(size_t)FS * BATCH * CPAD];      // [fs][b][c]
__device__ float g_rspart[FS * CPAD];                    // [fs][c]

// ---------------- Kernel 1: precomputed meta (transposed store) ----------------
__global__ void __launch_bounds__(1024) embed_k(const float* __restrict__ x,
                                                const float* __restrict__ mn,
                                                const float* __restrict__ mx) {
    __shared__ uint2 sm[32][33];
    const int tx = threadIdx.x & 31;
    const int ty = threadIdx.x >> 5;
    const int f0 = blockIdx.x * 32;
    const int b0 = blockIdx.y * 32;

    const float mnv = mn[0], mxv = mx[0];
    const float s = (x[(size_t)(b0 + ty) * FDIM + f0 + tx] - mnv) / (mxv - mnv) * 63.0f;

    uint2 m;
    if (s >= 0.0f && s <= 63.0f) {
        int t = (int)s;
        if (t > 62) t = 62;
        const float l0 = s - (float)t;                    // weight of vertex t+1
        const __half2 lam2 = __floats2half2_rn(1.0f - l0, l0);
        m.x = (uint32_t)t * (TSTRIDE * 4);
        m.y = *(const uint32_t*)&lam2;
    } else {
        m.x = 63u * (TSTRIDE * 4);                        // zero row sink
        m.y = 0u;                                         // zero lambda
    }
    sm[ty][tx] = m;
    __syncthreads();
    g_meta[(size_t)(f0 + ty) * BATCH + b0 + tx] = sm[tx][ty];
}

// ---------------- Kernel 2: f16-pair gather, 2 CTAs/SM, depth-2 prefetch ----------------
// CTA: 64 classes (cb) x 128 f (fs) x 128 b (bh). tile[t][c] = half2(W[c][t], W[c][t+1]).
// warp w (0..7) -> b in [bh*128+16w, +16); lane -> classes {lane, lane+32}.
__global__ void __launch_bounds__(THREADS, 2) gather_k(const float* __restrict__ W) {
    __shared__ uint32_t sm_tile[2][64 * TSTRIDE];   // 2 x 16.6 KB
    __shared__ uint2    sm_meta[2][128];            // 2 KB

    const int tid  = threadIdx.x;
    const int lane = tid & 31;
    const int w    = tid >> 5;       // 0..7
    const int ly   = lane >> 4;
    const int g    = lane & 15;
    const int bh   = blockIdx.x & 1;
    const int cb   = blockIdx.x >> 1;    // 0..15
    const int fs   = blockIdx.y;         // 0..7
    const int fbase = fs * FPC;

    // fill: pass p (0..3) -> class row p*16 + w*2 + ly, cols 4g..4g+3 (coalesced float4)
    int rl[4];
    const float* wp[4];
    #pragma unroll
    for (int p = 0; p < 4; p++) {
        rl[p] = p * 16 + w * 2 + ly;
        int row = cb * 64 + rl[p];
        if (row > NCLS - 1) row = NCLS - 1;
        wp[p] = W + (size_t)row * KROW + (size_t)fbase * 64 + g * 4;
    }
    const uint2* mp = g_meta + (size_t)fbase * BATCH + bh * 128 + tid;   // valid tid<128

    uint32_t acch[2][16];
    float    accf[2][16];
    #pragma unroll
    for (int k = 0; k < 2; k++)
        #pragma unroll
        for (int j = 0; j < 16; j++) { acch[k][j] = 0u; accf[k][j] = 0.f; }
    float rs[4] = {0.f, 0.f, 0.f, 0.f};

    // depth-2 prefetch registers
    float4 wvA[4], wvB[4];
    uint2 mA = make_uint2(0u, 0u), mB = make_uint2(0u, 0u);
    #pragma unroll
    for (int p = 0; p < 4; p++) {
        wvA[p] = *(const float4*)(wp[p]);
        wvB[p] = *(const float4*)(wp[p] + 64);
    }
    if (tid < 128) { mA = mp[0]; mB = mp[BATCH]; }

    auto phase = [&](int fi, float4* wv, uint2& mreg) {
        const int buf = fi & 1;
        // ---- fill pair tile + rowsum ----
        #pragma unroll
        for (int p = 0; p < 4; p++) {
            const float4 v = wv[p];
            const float nx = __shfl_down_sync(0xffffffffu, v.x, 1);
            rs[p] += (v.x + v.y) + (v.z + v.w);
            uint32_t pr[4]; __half2 h;
            h = __floats2half2_rn(v.x, v.y);  pr[0] = *(uint32_t*)&h;
            h = __floats2half2_rn(v.y, v.z);  pr[1] = *(uint32_t*)&h;
            h = __floats2half2_rn(v.z, v.w);  pr[2] = *(uint32_t*)&h;
            h = __floats2half2_rn(v.w, nx);   pr[3] = *(uint32_t*)&h;
            if (g == 15) pr[3] = 0u;          // t=63 row: zero sink
            #pragma unroll
            for (int i = 0; i < 4; i++)
                sm_tile[buf][(4 * g + i) * TSTRIDE + rl[p]] = pr[i];
        }
        if (tid < 128) sm_meta[buf][tid] = mreg;
        __syncthreads();

        // ---- refill this register set for fi+2 (guarded at slice edge) ----
        if (fi + 2 < FPC) {
            #pragma unroll
            for (int p = 0; p < 4; p++)
                wv[p] = *(const float4*)(wp[p] + (size_t)(fi + 2) * 64);
            if (tid < 128) mreg = mp[(size_t)(fi + 2) * BATCH];
        }

        // ---- gather: 16 b's; per b: 1 meta-broadcast + 2 LDS.32 + 2 HFMA2 ----
        const char* tb = (const char*)sm_tile[buf];
        const uint4* mb = (const uint4*)(sm_meta[buf] + w * 16);
        #pragma unroll
        for (int q = 0; q < 8; q++) {
            const uint4 mq = mb[q];
            {
                const int j = 2 * q;
                const uint32_t* pb = (const uint32_t*)(tb + mq.x) + lane;
                const uint32_t p0 = pb[0];
                const uint32_t p1 = pb[32];
                const __half2 l2 = *(const __half2*)&mq.y;
                __half2 a0 = *(__half2*)&acch[0][j];
                __half2 a1 = *(__half2*)&acch[1][j];
                a0 = __hfma2(l2, *(const __half2*)&p0, a0);
                a1 = __hfma2(l2, *(const __half2*)&p1, a1);
                acch[0][j] = *(uint32_t*)&a0;
                acch[1][j] = *(uint32_t*)&a1;
            }
            {
                const int j = 2 * q + 1;
                const uint32_t* pb = (const uint32_t*)(tb + mq.z) + lane;
                const uint32_t p0 = pb[0];
                const uint32_t p1 = pb[32];
                const __half2 l2 = *(const __half2*)&mq.w;
                __half2 a0 = *(__half2*)&acch[0][j];
                __half2 a1 = *(__half2*)&acch[1][j];
                a0 = __hfma2(l2, *(const __half2*)&p0, a0);
                a1 = __hfma2(l2, *(const __half2*)&p1, a1);
                acch[0][j] = *(uint32_t*)&a0;
                acch[1][j] = *(uint32_t*)&a1;
            }
        }

        // ---- drain f16 accumulators to fp32 every 16 f ----
        if ((fi & 15) == 15) {
            #pragma unroll
            for (int k = 0; k < 2; k++)
                #pragma unroll
                for (int j = 0; j < 16; j++) {
                    const float2 f2 = __half22float2(*(const __half2*)&acch[k][j]);
                    accf[k][j] += f2.x + f2.y;
                    acch[k][j] = 0u;
                }
        }
    };

    for (int fi2 = 0; fi2 < FPC / 2; fi2++) {
        phase(2 * fi2,     wvA, mA);
        phase(2 * fi2 + 1, wvB, mB);
    }

    // ---- rowsum: reduce over the 16 column groups ----
    #pragma unroll
    for (int p = 0; p < 4; p++) {
        float r = rs[p];
        r += __shfl_xor_sync(0xffffffffu, r, 1);
        r += __shfl_xor_sync(0xffffffffu, r, 2);
        r += __shfl_xor_sync(0xffffffffu, r, 4);
        r += __shfl_xor_sync(0xffffffffu, r, 8);
        if (g == 0 && bh == 0)
            g_rspart[fs * CPAD + cb * 64 + rl[p]] = r;
    }

    // ---- store partials (coalesced) ----
    #pragma unroll
    for (int j = 0; j < 16; j++) {
        float* pp = g_part + ((size_t)fs * BATCH + bh * 128 + w * 16 + j) * CPAD + cb * 64;
        pp[lane]      = accf[0][j];
        pp[lane + 32] = accf[1][j];
    }
}

// ---------------- Kernel 3: reduce partials + rowsum term ----------------
__global__ void __launch_bounds__(256) epi_k(const float* __restrict__ mn,
                                             const float* __restrict__ mx,
                                             float* __restrict__ out) {
    const int b = blockIdx.x;
    const float mnv = mn[0], mxv = mx[0];
    const float sc = mxv - mnv;
    for (int c = threadIdx.x; c < NCLS; c += 256) {
        float s = 0.f, rsum = 0.f;
        #pragma unroll
        for (int fsl = 0; fsl < FS; fsl++) {
            s    += g_part[((size_t)fsl * BATCH + b) * CPAD + c];
            rsum += g_rspart[fsl * CPAD + c];
        }
        out[(size_t)b * NCLS + c] = sc * s + mnv * rsum;
    }
}

// ---------------- launch ----------------
extern "C" void kernel_launch(void* const* d_in, const int* in_sizes, int n_in,
                              void* d_out, int out_size) {
    const float* x  = (const float*)d_in[0];
    const float* mn = (const float*)d_in[1];
    const float* mx = (const float*)d_in[2];
    const float* W  = (const float*)d_in[3];
    float* out = (float*)d_out;

    embed_k<<<dim3(32, 8), 1024>>>(x, mn, mx);
    gather_k<<<dim3(CB * 2, FS), THREADS>>>(W);
    epi_k<<<BATCH, 256>>>(mn, mx, out);
}

// round 8
// speedup vs baseline: 2.4176x; 2.4176x over previous
#include <cuda_runtime.h>
#include <cuda_fp16.h>
#include <stdint.h>

#define FDIM   1024
#define BATCH  256
#define NCLS   1000
#define CPAD   1024
#define KROW   65536
#define CB     16          // class blocks of 64
#define FS     8           // f slices of 128
#define FPC    128
#define THREADS 512
#define TSTRIDE 65         // pair-tile row stride in words
#define FTILE  (64 * TSTRIDE)

// ---------------- static device scratch ----------------
__device__ uint2 g_meta[FDIM * BATCH];                   // [f][b]: {t*260, half2(1-l0, l0)}
__device__ float g_part[(size_t)FS * BATCH * CPAD];      // [fs][b][c]
__device__ float g_rspart[FS * CPAD];                    // [fs][c]

// ---------------- Kernel 1: precomputed meta (transposed store) ----------------
__global__ void __launch_bounds__(1024) embed_k(const float* __restrict__ x,
                                                const float* __restrict__ mn,
                                                const float* __restrict__ mx) {
    __shared__ uint2 sm[32][33];
    const int tx = threadIdx.x & 31;
    const int ty = threadIdx.x >> 5;
    const int f0 = blockIdx.x * 32;
    const int b0 = blockIdx.y * 32;

    const float mnv = mn[0], mxv = mx[0];
    const float s = (x[(size_t)(b0 + ty) * FDIM + f0 + tx] - mnv) / (mxv - mnv) * 63.0f;

    uint2 m;
    if (s >= 0.0f && s <= 63.0f) {
        int t = (int)s;
        if (t > 62) t = 62;
        const float l0 = s - (float)t;                    // weight of vertex t+1
        const __half2 lam2 = __floats2half2_rn(1.0f - l0, l0);
        m.x = (uint32_t)t * (TSTRIDE * 4);
        m.y = *(const uint32_t*)&lam2;
    } else {
        m.x = 63u * (TSTRIDE * 4);                        // zero row sink
        m.y = 0u;                                         // zero lambda
    }
    sm[ty][tx] = m;
    __syncthreads();
    g_meta[(size_t)(f0 + ty) * BATCH + b0 + tx] = sm[tx][ty];
}

// ---------------- Kernel 2: f16-pair gather, 2-f epochs ----------------
// CTA: 64 classes (cb) x 128 f (fs) x 256 b. tile[f2][t][c] = half2(W[c][t], W[c][t+1]).
// Gather: warp w (0..15) -> b in [16w,16w+16); lane -> classes {lane, lane+32}.
__global__ void __launch_bounds__(THREADS, 1) gather_k(const float* __restrict__ W) {
    __shared__ uint32_t sm_tile[2][2 * FTILE];     // 2 bufs x 2 f x 16.6 KB
    __shared__ uint2    sm_meta[2][512];           // 2 bufs x 2 f x 256 b

    const int tid  = threadIdx.x;
    const int lane = tid & 31;
    const int w    = tid >> 5;       // 0..15
    const int ly   = lane >> 4;
    const int g    = lane & 15;
    const int cb   = blockIdx.x;     // 0..15
    const int fs   = blockIdx.y;     // 0..7
    const int fbase = fs * FPC;

    // fill: pass p (0..1) -> class row p*32 + w*2 + ly, cols 4g..4g+3 (coalesced float4)
    int rl[2];
    const float* wp[2];
    #pragma unroll
    for (int p = 0; p < 2; p++) {
        rl[p] = p * 32 + w * 2 + ly;
        int row = cb * 64 + rl[p];
        if (row > NCLS - 1) row = NCLS - 1;
        wp[p] = W + (size_t)row * KROW + (size_t)fbase * 64 + g * 4;
    }
    // meta: tid covers (f2 = tid>>8, b = tid&255)
    const uint2* mp = g_meta + (size_t)(fbase + (tid >> 8)) * BATCH + (tid & 255);

    uint32_t acch[2][16];
    float    accf[2][16];
    #pragma unroll
    for (int k = 0; k < 2; k++)
        #pragma unroll
        for (int j = 0; j < 16; j++) { acch[k][j] = 0u; accf[k][j] = 0.f; }
    float rs[2] = {0.f, 0.f};

    // prologue prefetch: epoch 0 (f = 0, 1)
    float4 wv[2][2];                                  // [p][f2]
    #pragma unroll
    for (int p = 0; p < 2; p++) {
        wv[p][0] = *(const float4*)(wp[p]);
        wv[p][1] = *(const float4*)(wp[p] + 64);
    }
    uint2 mreg = mp[0];

    for (int e = 0; e < FPC / 2; e++) {
        const int buf = e & 1;

        // ---- fill both pair sub-tiles + rowsum ----
        #pragma unroll
        for (int f2 = 0; f2 < 2; f2++) {
            uint32_t* tb = sm_tile[buf] + f2 * FTILE;
            #pragma unroll
            for (int p = 0; p < 2; p++) {
                const float4 v = wv[p][f2];
                const float nx = __shfl_down_sync(0xffffffffu, v.x, 1);
                rs[p] += (v.x + v.y) + (v.z + v.w);
                uint32_t pr[4]; __half2 h;
                h = __floats2half2_rn(v.x, v.y);  pr[0] = *(uint32_t*)&h;
                h = __floats2half2_rn(v.y, v.z);  pr[1] = *(uint32_t*)&h;
                h = __floats2half2_rn(v.z, v.w);  pr[2] = *(uint32_t*)&h;
                h = __floats2half2_rn(v.w, nx);   pr[3] = *(uint32_t*)&h;
                if (g == 15) pr[3] = 0u;          // t=63 row: zero sink
                #pragma unroll
                for (int i = 0; i < 4; i++)
                    tb[(4 * g + i) * TSTRIDE + rl[p]] = pr[i];
            }
        }
        sm_meta[buf][tid] = mreg;
        __syncthreads();

        // ---- refill registers for epoch e+1 (slack = 2 f of gather) ----
        if (e + 1 < FPC / 2) {
            const size_t off = (size_t)(2 * (e + 1)) * 64;
            #pragma unroll
            for (int p = 0; p < 2; p++) {
                wv[p][0] = *(const float4*)(wp[p] + off);
                wv[p][1] = *(const float4*)(wp[p] + off + 64);
            }
            mreg = mp[(size_t)(2 * (e + 1)) * BATCH];
        }

        // ---- gather both f's: per b: 2 conflict-free LDS.32 + 2 HFMA2 ----
        #pragma unroll
        for (int f2 = 0; f2 < 2; f2++) {
            const char* tb = (const char*)(sm_tile[buf] + f2 * FTILE);
            const uint4* mb = (const uint4*)(sm_meta[buf] + f2 * 256 + w * 16);
            #pragma unroll
            for (int q = 0; q < 8; q++) {
                const uint4 mq = mb[q];
                {
                    const int j = 2 * q;
                    const uint32_t* pb = (const uint32_t*)(tb + mq.x) + lane;
                    const uint32_t p0 = pb[0];
                    const uint32_t p1 = pb[32];
                    const __half2 l2 = *(const __half2*)&mq.y;
                    __half2 a0 = *(__half2*)&acch[0][j];
                    __half2 a1 = *(__half2*)&acch[1][j];
                    a0 = __hfma2(l2, *(const __half2*)&p0, a0);
                    a1 = __hfma2(l2, *(const __half2*)&p1, a1);
                    acch[0][j] = *(uint32_t*)&a0;
                    acch[1][j] = *(uint32_t*)&a1;
                }
                {
                    const int j = 2 * q + 1;
                    const uint32_t* pb = (const uint32_t*)(tb + mq.z) + lane;
                    const uint32_t p0 = pb[0];
                    const uint32_t p1 = pb[32];
                    const __half2 l2 = *(const __half2*)&mq.w;
                    __half2 a0 = *(__half2*)&acch[0][j];
                    __half2 a1 = *(__half2*)&acch[1][j];
                    a0 = __hfma2(l2, *(const __half2*)&p0, a0);
                    a1 = __hfma2(l2, *(const __half2*)&p1, a1);
                    acch[0][j] = *(uint32_t*)&a0;
                    acch[1][j] = *(uint32_t*)&a1;
                }
            }
        }

        // ---- drain f16 accumulators to fp32 every 8 epochs (16 f) ----
        if ((e & 7) == 7) {
            #pragma unroll
            for (int k = 0; k < 2; k++)
                #pragma unroll
                for (int j = 0; j < 16; j++) {
                    const float2 f2v = __half22float2(*(const __half2*)&acch[k][j]);
                    accf[k][j] += f2v.x + f2v.y;
                    acch[k][j] = 0u;
                }
        }
    }

    // ---- rowsum: reduce over the 16 column groups (xor masks stay in ly group) ----
    #pragma unroll
    for (int p = 0; p < 2; p++) {
        float r = rs[p];
        r += __shfl_xor_sync(0xffffffffu, r, 1);
        r += __shfl_xor_sync(0xffffffffu, r, 2);
        r += __shfl_xor_sync(0xffffffffu, r, 4);
        r += __shfl_xor_sync(0xffffffffu, r, 8);
        if (g == 0)
            g_rspart[fs * CPAD + cb * 64 + rl[p]] = r;
    }

    // ---- store partials (coalesced 128B per half) ----
    #pragma unroll
    for (int j = 0; j < 16; j++) {
        float* pp = g_part + ((size_t)fs * BATCH + w * 16 + j) * CPAD + cb * 64;
        pp[lane]      = accf[0][j];
        pp[lane + 32] = accf[1][j];
    }
}

// ---------------- Kernel 3: reduce partials + rowsum term ----------------
__global__ void __launch_bounds__(256) epi_k(const float* __restrict__ mn,
                                             const float* __restrict__ mx,
                                             float* __restrict__ out) {
    const int b = blockIdx.x;
    const float mnv = mn[0], mxv = mx[0];
    const float sc = mxv - mnv;
    for (int c = threadIdx.x; c < NCLS; c += 256) {
        float s = 0.f, rsum = 0.f;
        #pragma unroll
        for (int fsl = 0; fsl < FS; fsl++) {
            s    += g_part[((size_t)fsl * BATCH + b) * CPAD + c];
            rsum += g_rspart[fsl * CPAD + c];
        }
        out[(size_t)b * NCLS + c] = sc * s + mnv * rsum;
    }
}

// ---------------- launch ----------------
extern "C" void kernel_launch(void* const* d_in, const int* in_sizes, int n_in,
                              void* d_out, int out_size) {
    const float* x  = (const float*)d_in[0];
    const float* mn = (const float*)d_in[1];
    const float* mx = (const float*)d_in[2];
    const float* W  = (const float*)d_in[3];
    float* out = (float*)d_out;

    embed_k<<<dim3(32, 8), 1024>>>(x, mn, mx);
    gather_k<<<dim3(CB, FS), THREADS>>>(W);
    epi_k<<<BATCH, 256>>>(mn, mx, out);
}

// round 9
// speedup vs baseline: 2.4739x; 1.0233x over previous
#include <cuda_runtime.h>
#include <cuda_fp16.h>
#include <stdint.h>

#define FDIM   1024
#define BATCH  256
#define NCLS   1000
#define CPAD   1024
#define KROW   65536
#define CB     16          // class blocks of 64
#define FS     8           // f slices of 128
#define FPC    128
#define THREADS 512
#define TSTRIDE 65         // pair-tile row stride in words
#define FTILE  (64 * TSTRIDE)          // words per f-tile (4160)
#define EPOCH_F 4
#define NEPOCH (FPC / EPOCH_F)         // 32

// dynamic smem layout (words):
//   tiles: [2 bufs][EPOCH_F][FTILE]            = 2*4*4160 words
//   meta : [2 bufs][EPOCH_F*256] uint2, after tiles
#define TILE_WORDS (2 * EPOCH_F * FTILE)
#define META_OFF_W TILE_WORDS
#define SMEM_BYTES (TILE_WORDS * 4 + 2 * EPOCH_F * 256 * 8)   // 149504

// ---------------- static device scratch ----------------
__device__ uint2 g_meta[FDIM * BATCH];                   // [f][b]: {t*260, half2(1-l0, l0)}
__device__ float g_part[(size_t)FS * BATCH * CPAD];      // [fs][b][c]
__device__ float g_rspart[FS * CPAD];                    // [fs][c]

// ---------------- Kernel 1: precomputed meta (transposed store) ----------------
__global__ void __launch_bounds__(1024) embed_k(const float* __restrict__ x,
                                                const float* __restrict__ mn,
                                                const float* __restrict__ mx) {
    __shared__ uint2 sm[32][33];
    const int tx = threadIdx.x & 31;
    const int ty = threadIdx.x >> 5;
    const int f0 = blockIdx.x * 32;
    const int b0 = blockIdx.y * 32;

    const float mnv = mn[0], mxv = mx[0];
    const float s = (x[(size_t)(b0 + ty) * FDIM + f0 + tx] - mnv) / (mxv - mnv) * 63.0f;

    uint2 m;
    if (s >= 0.0f && s <= 63.0f) {
        int t = (int)s;
        if (t > 62) t = 62;
        const float l0 = s - (float)t;                    // weight of vertex t+1
        const __half2 lam2 = __floats2half2_rn(1.0f - l0, l0);
        m.x = (uint32_t)t * (TSTRIDE * 4);
        m.y = *(const uint32_t*)&lam2;
    } else {
        m.x = 63u * (TSTRIDE * 4);                        // zero row sink
        m.y = 0u;                                         // zero lambda
    }
    sm[ty][tx] = m;
    __syncthreads();
    g_meta[(size_t)(f0 + ty) * BATCH + b0 + tx] = sm[tx][ty];
}

// ---------------- Kernel 2: f16-pair gather, 4-f epochs ----------------
// CTA: 64 classes (cb) x 128 f (fs) x 256 b. tile[f4][t][c] = half2(W[c][t], W[c][t+1]).
// Gather: warp w (0..15) -> b in [16w,16w+16); lane -> classes {lane, lane+32}.
__global__ void __launch_bounds__(THREADS, 1) gather_k(const float* __restrict__ W) {
    extern __shared__ uint32_t smw[];
    uint32_t* tiles = smw;
    uint2*    meta  = (uint2*)(smw + META_OFF_W);

    const int tid  = threadIdx.x;
    const int lane = tid & 31;
    const int w    = tid >> 5;       // 0..15
    const int ly   = lane >> 4;
    const int g    = lane & 15;
    const int cb   = blockIdx.x;     // 0..15
    const int fs   = blockIdx.y;     // 0..7
    const int fbase = fs * FPC;

    // fill: pass p (0..1) -> class row p*32 + w*2 + ly, cols 4g..4g+3 (coalesced float4)
    int rl[2];
    const float* wp[2];
    #pragma unroll
    for (int p = 0; p < 2; p++) {
        rl[p] = p * 32 + w * 2 + ly;
        int row = cb * 64 + rl[p];
        if (row > NCLS - 1) row = NCLS - 1;
        wp[p] = W + (size_t)row * KROW + (size_t)fbase * 64 + g * 4;
    }
    // meta: thread covers entries tid and tid+512 of each epoch's 1024
    const uint2* mp0 = g_meta + (size_t)(fbase + (tid >> 8)) * BATCH + (tid & 255);
    const uint2* mp1 = mp0 + 2 * BATCH;

    uint32_t acch[2][16];
    float    accf[2][16];
    #pragma unroll
    for (int k = 0; k < 2; k++)
        #pragma unroll
        for (int j = 0; j < 16; j++) { acch[k][j] = 0u; accf[k][j] = 0.f; }
    float rs[2] = {0.f, 0.f};

    // prologue prefetch: epoch 0 (f = 0..3)
    float4 wv[2][EPOCH_F];
    #pragma unroll
    for (int p = 0; p < 2; p++)
        #pragma unroll
        for (int f4 = 0; f4 < EPOCH_F; f4++)
            wv[p][f4] = *(const float4*)(wp[p] + f4 * 64);
    uint2 mr0 = mp0[0], mr1 = mp1[0];

    for (int e = 0; e < NEPOCH; e++) {
        const int buf = e & 1;
        uint32_t* tbase = tiles + buf * (EPOCH_F * FTILE);

        // ---- fill all pair sub-tiles + rowsum ----
        #pragma unroll
        for (int f4 = 0; f4 < EPOCH_F; f4++) {
            uint32_t* tb = tbase + f4 * FTILE;
            #pragma unroll
            for (int p = 0; p < 2; p++) {
                const float4 v = wv[p][f4];
                const float nx = __shfl_down_sync(0xffffffffu, v.x, 1);
                rs[p] += (v.x + v.y) + (v.z + v.w);
                uint32_t pr[4]; __half2 h;
                h = __floats2half2_rn(v.x, v.y);  pr[0] = *(uint32_t*)&h;
                h = __floats2half2_rn(v.y, v.z);  pr[1] = *(uint32_t*)&h;
                h = __floats2half2_rn(v.z, v.w);  pr[2] = *(uint32_t*)&h;
                h = __floats2half2_rn(v.w, nx);   pr[3] = *(uint32_t*)&h;
                if (g == 15) pr[3] = 0u;          // t=63 row: zero sink
                #pragma unroll
                for (int i = 0; i < 4; i++)
                    tb[(4 * g + i) * TSTRIDE + rl[p]] = pr[i];
            }
        }
        meta[buf * (EPOCH_F * 256) + tid]       = mr0;
        meta[buf * (EPOCH_F * 256) + tid + 512] = mr1;
        __syncthreads();

        // ---- refill registers for epoch e+1 (slack = 4 f of gather) ----
        if (e + 1 < NEPOCH) {
            const size_t off = (size_t)(EPOCH_F * (e + 1)) * 64;
            #pragma unroll
            for (int p = 0; p < 2; p++)
                #pragma unroll
                for (int f4 = 0; f4 < EPOCH_F; f4++)
                    wv[p][f4] = *(const float4*)(wp[p] + off + f4 * 64);
            mr0 = mp0[(size_t)(EPOCH_F * (e + 1)) * BATCH];
            mr1 = mp1[(size_t)(EPOCH_F * (e + 1)) * BATCH];
        }

        // ---- gather 4 f's: per b: 2 conflict-free LDS.32 + 2 HFMA2 ----
        #pragma unroll
        for (int f4 = 0; f4 < EPOCH_F; f4++) {
            const char* tb = (const char*)(tbase + f4 * FTILE);
            const uint4* mb = (const uint4*)(meta + buf * (EPOCH_F * 256) + f4 * 256 + w * 16);
            #pragma unroll
            for (int q = 0; q < 8; q++) {
                const uint4 mq = mb[q];
                {
                    const int j = 2 * q;
                    const uint32_t* pb = (const uint32_t*)(tb + mq.x) + lane;
                    const uint32_t p0 = pb[0];
                    const uint32_t p1 = pb[32];
                    const __half2 l2 = *(const __half2*)&mq.y;
                    __half2 a0 = *(__half2*)&acch[0][j];
                    __half2 a1 = *(__half2*)&acch[1][j];
                    a0 = __hfma2(l2, *(const __half2*)&p0, a0);
                    a1 = __hfma2(l2, *(const __half2*)&p1, a1);
                    acch[0][j] = *(uint32_t*)&a0;
                    acch[1][j] = *(uint32_t*)&a1;
                }
                {
                    const int j = 2 * q + 1;
                    const uint32_t* pb = (const uint32_t*)(tb + mq.z) + lane;
                    const uint32_t p0 = pb[0];
                    const uint32_t p1 = pb[32];
                    const __half2 l2 = *(const __half2*)&mq.w;
                    __half2 a0 = *(__half2*)&acch[0][j];
                    __half2 a1 = *(__half2*)&acch[1][j];
                    a0 = __hfma2(l2, *(const __half2*)&p0, a0);
                    a1 = __hfma2(l2, *(const __half2*)&p1, a1);
                    acch[0][j] = *(uint32_t*)&a0;
                    acch[1][j] = *(uint32_t*)&a1;
                }
            }
        }

        // ---- drain f16 accumulators to fp32 every 4 epochs (16 f) ----
        if ((e & 3) == 3) {
            #pragma unroll
            for (int k = 0; k < 2; k++)
                #pragma unroll
                for (int j = 0; j < 16; j++) {
                    const float2 f2v = __half22float2(*(const __half2*)&acch[k][j]);
                    accf[k][j] += f2v.x + f2v.y;
                    acch[k][j] = 0u;
                }
        }
    }

    // ---- rowsum: reduce over the 16 column groups ----
    #pragma unroll
    for (int p = 0; p < 2; p++) {
        float r = rs[p];
        r += __shfl_xor_sync(0xffffffffu, r, 1);
        r += __shfl_xor_sync(0xffffffffu, r, 2);
        r += __shfl_xor_sync(0xffffffffu, r, 4);
        r += __shfl_xor_sync(0xffffffffu, r, 8);
        if (g == 0)
            g_rspart[fs * CPAD + cb * 64 + rl[p]] = r;
    }

    // ---- store partials (coalesced 128B per half) ----
    #pragma unroll
    for (int j = 0; j < 16; j++) {
        float* pp = g_part + ((size_t)fs * BATCH + w * 16 + j) * CPAD + cb * 64;
        pp[lane]      = accf[0][j];
        pp[lane + 32] = accf[1][j];
    }
}

// ---------------- Kernel 3: reduce partials + rowsum term ----------------
__global__ void __launch_bounds__(256) epi_k(const float* __restrict__ mn,
                                             const float* __restrict__ mx,
                                             float* __restrict__ out) {
    const int b = blockIdx.x;
    const float mnv = mn[0], mxv = mx[0];
    const float sc = mxv - mnv;
    for (int c = threadIdx.x; c < NCLS; c += 256) {
        float s = 0.f, rsum = 0.f;
        #pragma unroll
        for (int fsl = 0; fsl < FS; fsl++) {
            s    += g_part[((size_t)fsl * BATCH + b) * CPAD + c];
            rsum += g_rspart[fsl * CPAD + c];
        }
        out[(size_t)b * NCLS + c] = sc * s + mnv * rsum;
    }
}

// ---------------- launch ----------------
extern "C" void kernel_launch(void* const* d_in, const int* in_sizes, int n_in,
                              void* d_out, int out_size) {
    const float* x  = (const float*)d_in[0];
    const float* mn = (const float*)d_in[1];
    const float* mx = (const float*)d_in[2];
    const float* W  = (const float*)d_in[3];
    float* out = (float*)d_out;

    embed_k<<<dim3(32, 8), 1024>>>(x, mn, mx);

    cudaFuncSetAttribute(gather_k, cudaFuncAttributeMaxDynamicSharedMemorySize, SMEM_BYTES);
    gather_k<<<dim3(CB, FS), THREADS, SMEM_BYTES>>>(W);

    epi_k<<<BATCH, 256>>>(mn, mx, out);
}